// round 6
// baseline (speedup 1.0000x reference)
#include <cuda_runtime.h>
#include <cstdint>

#define BB     16
#define NIN    1024
#define MM     512
#define NCHUNK 8
#define CHUNK  (NIN / NCHUNK)   // 128
#define LOG2E  1.4426950408889634f
#define LN_EPS 1e-5f

typedef unsigned long long u64;

// Deterministic per-chunk partial accumulators for nv: [chunk][b][m][16]
__device__ float g_partial[NCHUNK * BB * MM * 16];

__device__ __forceinline__ u64 pack2(float lo, float hi) {
    u64 r; asm("mov.b64 %0,{%1,%2};" : "=l"(r) : "f"(lo), "f"(hi)); return r;
}
__device__ __forceinline__ void unpack2(u64 v, float& lo, float& hi) {
    asm("mov.b64 {%0,%1},%2;" : "=f"(lo), "=f"(hi) : "l"(v));
}
__device__ __forceinline__ u64 fma2(u64 a, u64 b, u64 c) {
    u64 d; asm("fma.rn.f32x2 %0,%1,%2,%3;" : "=l"(d) : "l"(a), "l"(b), "l"(c)); return d;
}
__device__ __forceinline__ u64 add2(u64 a, u64 b) {
    u64 d; asm("add.rn.f32x2 %0,%1,%2;" : "=l"(d) : "l"(a), "l"(b)); return d;
}
__device__ __forceinline__ u64 mul2(u64 a, u64 b) {
    u64 d; asm("mul.rn.f32x2 %0,%1,%2;" : "=l"(d) : "l"(a), "l"(b)); return d;
}
__device__ __forceinline__ float ex2f(float x) {
    float y; asm("ex2.approx.f32 %0,%1;" : "=f"(y) : "f"(x)); return y;
}
__device__ __forceinline__ float rcpf(float x) {
    float y; asm("rcp.approx.f32 %0,%1;" : "=f"(y) : "f"(x)); return y;
}
__device__ __forceinline__ void stcs(float* p, float v) {
    asm volatile("st.global.cs.f32 [%0],%1;" :: "l"(p), "f"(v) : "memory");
}
// Named split barriers (ids 1,2; count = 512 arrives + 512 syncs = 1024).
__device__ __forceinline__ void bar_arrive(int id) {
    asm volatile("bar.arrive %0, 1024;" :: "r"(id) : "memory");
}
__device__ __forceinline__ void bar_wait(int id) {
    asm volatile("bar.sync %0, 1024;" :: "r"(id) : "memory");
}

// One CTA per (b, chunk). Thread = output capsule m. Per iteration i:
//   [wpair pack | w prefetch | pose FMAs]  <- runs PAST a slow warp (drift window)
//   bar.sync(prev)  -> consume S_{i-1}: acc += (1/S_{i-1}) * P_{i-1}
//   exp -> inner softmax -> agreement -> stage P_i = (eag*inv)*e2
//   warp-reduce exp(ag); lane0 STS partial; bar.arrive(cur)
// The split barrier lets warps drift ~40% of an iteration apart, so one warp's
// FMA-heavy pose window overlaps another's MUFU-heavy exp window (the round-5
// lockstep kept both pipes alternating idle).
__global__ __launch_bounds__(512, 1)
void caps_main(const float* __restrict__ x,     // [B, NIN, 16]
               const float* __restrict__ w,     // [NIN, 4, 4, MM]
               const float* __restrict__ V,     // [MM, 16]
               float* __restrict__ agree_out)   // [B, NIN, MM]
{
    __shared__ u64  xsd[CHUNK][16];   // dup-packed, LOG2E-prescaled x (16 KB)
    __shared__ float sred[2][16];     // [buf][warp]

    const int tid   = threadIdx.x;          // m
    const int wid   = tid >> 5;
    const int lane  = tid & 31;
    const int chunk = blockIdx.x % NCHUNK;
    const int b     = blockIdx.x / NCHUNK;   // 0..15
    const int n0    = chunk * CHUNK;

    // Stage + rescale + duplicate x into shared.
    for (int idx = tid; idx < CHUNK * 16; idx += 512) {
        const int i = idx >> 4;
        const int j = idx & 15;
        const float v = x[(((size_t)b * NIN) + n0 + i) * 16 + j] * LOG2E;
        xsd[i][j] = pack2(v, v);
    }
    // Seed buf1 so iteration 0's consume is a no-op (P starts at 0).
    if (tid < 16) sred[1][tid] = 1.0f;

    // Packed initial query: Vq2[a*2+dp] = {V[m][a*4+2dp], V[m][a*4+2dp+1]}.
    u64 Vq2[8];
    {
        const float* vm = V + (size_t)tid * 16;
#pragma unroll
        for (int k = 0; k < 8; k++) Vq2[k] = pack2(vm[2 * k], vm[2 * k + 1]);
    }

    u64 acc2[8];   // running nv accumulator (u64[8] == float[16] natural order)
    u64 P[8];      // staged (eag*inv)*e2 awaiting 1/S from the block reduce
#pragma unroll
    for (int k = 0; k < 8; k++) { acc2[k] = 0ull; P[k] = 0ull; }

    __syncthreads();
    bar_arrive(2);   // prime buf1's barrier for iteration 0's sync

    const float* wbase = w + (size_t)n0 * (16 * MM) + tid;
    float* agp = agree_out + (((size_t)b * NIN) + n0) * MM + tid;

    // Prefetch w for iteration 0.
    float wn[16];
#pragma unroll
    for (int s = 0; s < 16; s++) wn[s] = wbase[(size_t)s * MM];

    for (int i = 0; i < CHUNK; i++) {
        // ---- Drift window: pack w, prefetch next w, pose transform. ----
        u64 wpair[8];
#pragma unroll
        for (int k = 0; k < 8; k++) wpair[k] = pack2(wn[2 * k], wn[2 * k + 1]);
        if (i + 1 < CHUNK) {
            const float* wp = wbase + (size_t)(i + 1) * 16 * MM;
#pragma unroll
            for (int s = 0; s < 16; s++) wn[s] = wp[(size_t)s * MM];
        }

        u64 t2[8];
#pragma unroll
        for (int a = 0; a < 4; a++) {
#pragma unroll
            for (int dp = 0; dp < 2; dp++) {
                u64 acc = mul2(xsd[i][a * 4 + 0], wpair[0 * 2 + dp]);
                acc = fma2(xsd[i][a * 4 + 1], wpair[1 * 2 + dp], acc);
                acc = fma2(xsd[i][a * 4 + 2], wpair[2 * 2 + dp], acc);
                acc = fma2(xsd[i][a * 4 + 3], wpair[3 * 2 + dp], acc);
                t2[a * 2 + dp] = acc;
            }
        }

        // ---- Rendezvous with the PREVIOUS iteration's partials; consume. ----
        bar_wait(1 + ((i + 1) & 1));
        {
            float z = sred[(i + 1) & 1][lane & 15];
            z += __shfl_xor_sync(0xffffffffu, z, 1);
            z += __shfl_xor_sync(0xffffffffu, z, 2);
            z += __shfl_xor_sync(0xffffffffu, z, 4);
            z += __shfl_xor_sync(0xffffffffu, z, 8);
            const float r = rcpf(z);
            const u64 rd = pack2(r, r);
#pragma unroll
            for (int k = 0; k < 8; k++) acc2[k] = fma2(rd, P[k], acc2[k]);
        }

        // ---- exp (log2-domain) into P (e2 lives there transiently). ----
#pragma unroll
        for (int k = 0; k < 8; k++) {
            float lo, hi; unpack2(t2[k], lo, hi);
            P[k] = pack2(ex2f(lo), ex2f(hi));
        }
        // Inner-softmax denominator.
        u64 s01 = add2(add2(P[0], P[1]), add2(P[2], P[3]));
        u64 s23 = add2(add2(P[4], P[5]), add2(P[6], P[7]));
        u64 st  = add2(s01, s23);
        float slo, shi; unpack2(st, slo, shi);
        const float inv = rcpf(slo + shi);
        // Agreement dot with Vq.
        u64 g = mul2(P[0], Vq2[0]);
#pragma unroll
        for (int k = 1; k < 8; k++) g = fma2(P[k], Vq2[k], g);
        float glo, ghi; unpack2(g, glo, ghi);
        const float ag = (glo + ghi) * inv;
        stcs(agp + (size_t)i * MM, ag);
        const float e = ex2f(ag * LOG2E);   // |ag| <= 1, max-free softmax safe
        // Stage P_i = (eag*inv) * e2, in place.
        const float s = e * inv;
        const u64 sd = pack2(s, s);
#pragma unroll
        for (int k = 0; k < 8; k++) P[k] = mul2(sd, P[k]);

        // ---- Publish this iteration's warp partial of sum_m exp(ag). ----
        float v = e;
#pragma unroll
        for (int o = 16; o > 0; o >>= 1) v += __shfl_xor_sync(0xffffffffu, v, o);
        if (lane == 0) sred[i & 1][wid] = v;
        bar_arrive(1 + (i & 1));
    }

    // Final consume for iteration CHUNK-1.
    bar_wait(1 + ((CHUNK - 1) & 1));
    {
        float z = sred[(CHUNK - 1) & 1][lane & 15];
        z += __shfl_xor_sync(0xffffffffu, z, 1);
        z += __shfl_xor_sync(0xffffffffu, z, 2);
        z += __shfl_xor_sync(0xffffffffu, z, 4);
        z += __shfl_xor_sync(0xffffffffu, z, 8);
        const float r = rcpf(z);
        const u64 rd = pack2(r, r);
#pragma unroll
        for (int k = 0; k < 8; k++) acc2[k] = fma2(rd, P[k], acc2[k]);
    }

    // acc2 as u64[8] is already float[16] in natural slot order.
    {
        float4* dst = (float4*)(g_partial +
            ((((size_t)chunk * BB + b) * MM + tid) << 4));
#pragma unroll
        for (int q = 0; q < 4; q++) {
            float xx, yy, zz, ww;
            unpack2(acc2[2 * q],     xx, yy);
            unpack2(acc2[2 * q + 1], zz, ww);
            dst[q] = make_float4(xx, yy, zz, ww);
        }
    }
}

// Reduce chunk partials + LayerNorm. 8 lanes cooperate per (b,m) row:
// q = float4 quarter (0..3), h = chunk half (0..1, 4 chunks each).
__global__ __launch_bounds__(256)
void caps_ln(const float* __restrict__ gamma,
             const float* __restrict__ beta,
             float* __restrict__ nv_out)  // [B*MM, 16]
{
    const int t   = blockIdx.x * 256 + threadIdx.x;  // 0 .. B*MM*8-1
    const int row = t >> 3;
    const int q   = t & 3;
    const int h   = (t >> 2) & 1;
    const int b   = row / MM;
    const int m   = row % MM;

    float4 v = make_float4(0.f, 0.f, 0.f, 0.f);
#pragma unroll
    for (int cc = 0; cc < NCHUNK / 2; cc++) {
        const int c = h * (NCHUNK / 2) + cc;
        const float4 p = *(const float4*)(g_partial +
            ((((size_t)c * BB + b) * MM + m) << 4) + q * 4);
        v.x += p.x; v.y += p.y; v.z += p.z; v.w += p.w;
    }
    // Combine chunk halves (lanes differ in bit 2).
    v.x += __shfl_xor_sync(0xffffffffu, v.x, 4);
    v.y += __shfl_xor_sync(0xffffffffu, v.y, 4);
    v.z += __shfl_xor_sync(0xffffffffu, v.z, 4);
    v.w += __shfl_xor_sync(0xffffffffu, v.w, 4);

    // Row stats across the 4 q-lanes (bits 0-1).
    float s = v.x + v.y + v.z + v.w;
    s += __shfl_xor_sync(0xffffffffu, s, 1);
    s += __shfl_xor_sync(0xffffffffu, s, 2);
    const float mu = s * (1.0f / 16.0f);

    const float d0 = v.x - mu, d1 = v.y - mu, d2 = v.z - mu, d3 = v.w - mu;
    float ss = d0 * d0 + d1 * d1 + d2 * d2 + d3 * d3;
    ss += __shfl_xor_sync(0xffffffffu, ss, 1);
    ss += __shfl_xor_sync(0xffffffffu, ss, 2);
    const float rs = rsqrtf(ss * (1.0f / 16.0f) + LN_EPS);

    if (h == 0) {
        const float4 gm = *(const float4*)(gamma + q * 4);
        const float4 bt = *(const float4*)(beta + q * 4);
        float4 o;
        o.x = d0 * rs * gm.x + bt.x;
        o.y = d1 * rs * gm.y + bt.y;
        o.z = d2 * rs * gm.z + bt.z;
        o.w = d3 * rs * gm.w + bt.w;
        *(float4*)(nv_out + (size_t)row * 16 + q * 4) = o;
    }
}

extern "C" void kernel_launch(void* const* d_in, const int* in_sizes, int n_in,
                              void* d_out, int out_size)
{
    // metadata order: input, num_iter, w, V, gamma, beta
    const float* x     = (const float*)d_in[0];
    const float* w     = (const float*)d_in[2];
    const float* V     = (const float*)d_in[3];
    const float* gamma = (const float*)d_in[4];
    const float* beta  = (const float*)d_in[5];

    float* out    = (float*)d_out;
    float* nv_out = out;                          // [16,512,16]   = 131072
    float* agree  = out + (size_t)BB * MM * 16;   // [16,1024,512] = 8388608

    caps_main<<<NCHUNK * BB, 512>>>(x, w, V, agree);
    caps_ln<<<(BB * MM * 8) / 256, 256>>>(gamma, beta, nv_out);
}

// round 7
// speedup vs baseline: 1.1698x; 1.1698x over previous
#include <cuda_runtime.h>
#include <cstdint>

#define BB     16
#define NIN    1024
#define MM     512
#define NCHUNK 16
#define CHUNK  (NIN / NCHUNK)   // 64
#define BPG    2                // batches per CTA (register budget bound)
#define LOG2E  1.4426950408889634f
#define LN_EPS 1e-5f

typedef unsigned long long u64;

// Deterministic per-chunk partial accumulators for nv: [chunk][b][m][16]
__device__ float g_partial[NCHUNK * BB * MM * 16];

__device__ __forceinline__ u64 pack2(float lo, float hi) {
    u64 r; asm("mov.b64 %0,{%1,%2};" : "=l"(r) : "f"(lo), "f"(hi)); return r;
}
__device__ __forceinline__ void unpack2(u64 v, float& lo, float& hi) {
    asm("mov.b64 {%0,%1},%2;" : "=f"(lo), "=f"(hi) : "l"(v));
}
__device__ __forceinline__ u64 fma2(u64 a, u64 b, u64 c) {
    u64 d; asm("fma.rn.f32x2 %0,%1,%2,%3;" : "=l"(d) : "l"(a), "l"(b), "l"(c)); return d;
}
__device__ __forceinline__ u64 add2(u64 a, u64 b) {
    u64 d; asm("add.rn.f32x2 %0,%1,%2;" : "=l"(d) : "l"(a), "l"(b)); return d;
}
__device__ __forceinline__ u64 mul2(u64 a, u64 b) {
    u64 d; asm("mul.rn.f32x2 %0,%1,%2;" : "=l"(d) : "l"(a), "l"(b)); return d;
}
__device__ __forceinline__ float ex2f(float x) {
    float y; asm("ex2.approx.f32 %0,%1;" : "=f"(y) : "f"(x)); return y;
}
__device__ __forceinline__ float rcpf(float x) {
    float y; asm("rcp.approx.f32 %0,%1;" : "=f"(y) : "f"(x)); return y;
}
__device__ __forceinline__ void stcs(float* p, float v) {
    asm volatile("st.global.cs.f32 [%0],%1;" :: "l"(p), "f"(v) : "memory");
}

// Pairing: pair index k = a*2 + dp packs logical slots (a*4+2dp, a*4+2dp+1).
// Pipeline: iteration i FIRST consumes iteration i-1's block sum S (reading the
// other sred buffer — its barrier already passed) folding acc += s*E where
// s = eag_prev*inv_prev*rcp(S) (all scalar; E holds RAW e2, so this pipeline
// adds ZERO packed-FMA work vs the round-4 flow — round 5's regression came
// from the 8 extra mul2 of pre-scaled P staging). The consume's LDS/shfl chain
// overlaps the new iteration's independent w-pack + pose FMAs.
__global__ __launch_bounds__(512, 1)
void caps_main(const float* __restrict__ x,     // [B, NIN, 16]
               const float* __restrict__ w,     // [NIN, 4, 4, MM]
               const float* __restrict__ V,     // [MM, 16]
               float* __restrict__ agree_out)   // [B, NIN, MM]
{
    __shared__ u64  xsd[BPG][CHUNK][16];  // dup-packed, LOG2E-prescaled x (16 KB)
    __shared__ float sred[2][32];         // [buf][bb*16 + wid]

    const int tid   = threadIdx.x;          // m
    const int wid   = tid >> 5;
    const int lane  = tid & 31;
    const int chunk = blockIdx.x % NCHUNK;
    const int bp    = blockIdx.x / NCHUNK;  // 0..7
    const int b0    = bp * BPG;
    const int n0    = chunk * CHUNK;

    // Stage + rescale + duplicate x into shared.
    for (int idx = tid; idx < BPG * CHUNK * 16; idx += 512) {
        const int bb  = idx / (CHUNK * 16);
        const int rem = idx % (CHUNK * 16);
        const int i   = rem >> 4;
        const int j   = rem & 15;
        const float v = x[(((size_t)(b0 + bb) * NIN) + n0 + i) * 16 + j] * LOG2E;
        xsd[bb][i][j] = pack2(v, v);
    }
    // Seed the "previous" buffer so iteration 0's consume is a no-op
    // (eag_p = 0 -> s = 0, acc += 0*E).
    if (tid < 32) sred[1][tid] = 1.0f;

    // Packed initial query: Vq2[a*2+dp] = {V[m][a*4+2dp], V[m][a*4+2dp+1]}.
    u64 Vq2[8];
    {
        const float* vm = V + (size_t)tid * 16;
#pragma unroll
        for (int k = 0; k < 8; k++) Vq2[k] = pack2(vm[2 * k], vm[2 * k + 1]);
    }

    u64 acc2[BPG][8];   // running nv accumulator (u64[8] == float[16])
    u64 E[BPG][8];      // staged RAW e2 of the previous iteration
    float eag_p[BPG], inv_p[BPG];
#pragma unroll
    for (int bb = 0; bb < BPG; bb++) {
#pragma unroll
        for (int k = 0; k < 8; k++) { acc2[bb][k] = 0ull; E[bb][k] = 0ull; }
        eag_p[bb] = 0.f; inv_p[bb] = 1.f;
    }

    __syncthreads();

    const float* wbase = w + (size_t)n0 * (16 * MM) + tid;

    // Prefetch w for iteration 0.
    float wn[16];
#pragma unroll
    for (int s = 0; s < 16; s++) wn[s] = wbase[(size_t)s * MM];

    for (int i = 0; i < CHUNK; i++) {
        // ---- Consume iteration i-1: acc += (eag_p*inv_p*rcp(S)) * E. ----
        // sred[(i+1)&1] was published before the barrier that ended iter i-1.
        {
            float z = sred[(i + 1) & 1][lane];
#pragma unroll
            for (int o = 8; o > 0; o >>= 1) z += __shfl_xor_sync(0xffffffffu, z, o);
            const float s0 = eag_p[0] * inv_p[0] * rcpf(__shfl_sync(0xffffffffu, z, 0));
            const float s1 = eag_p[1] * inv_p[1] * rcpf(__shfl_sync(0xffffffffu, z, 16));
            const u64 s0d = pack2(s0, s0);
            const u64 s1d = pack2(s1, s1);
#pragma unroll
            for (int k = 0; k < 8; k++) {
                acc2[0][k] = fma2(s0d, E[0][k], acc2[0][k]);
                acc2[1][k] = fma2(s1d, E[1][k], acc2[1][k]);
            }
        }

        // ---- Pack current w; prefetch next iteration's w. ----
        u64 wpair[8];
#pragma unroll
        for (int k = 0; k < 8; k++) wpair[k] = pack2(wn[2 * k], wn[2 * k + 1]);
        if (i + 1 < CHUNK) {
            const float* wp = wbase + (size_t)(i + 1) * 16 * MM;
#pragma unroll
            for (int s = 0; s < 16; s++) wn[s] = wp[(size_t)s * MM];
        }

        // ---- Pose -> exp -> agreement; stage raw e2 + scalars. ----
        float eag[BPG];
#pragma unroll
        for (int bb = 0; bb < BPG; bb++) {
            u64 t2[8];
#pragma unroll
            for (int a = 0; a < 4; a++) {
#pragma unroll
                for (int dp = 0; dp < 2; dp++) {
                    u64 acc = mul2(xsd[bb][i][a * 4 + 0], wpair[0 * 2 + dp]);
                    acc = fma2(xsd[bb][i][a * 4 + 1], wpair[1 * 2 + dp], acc);
                    acc = fma2(xsd[bb][i][a * 4 + 2], wpair[2 * 2 + dp], acc);
                    acc = fma2(xsd[bb][i][a * 4 + 3], wpair[3 * 2 + dp], acc);
                    t2[a * 2 + dp] = acc;
                }
            }
            // exp (log2-domain) into E (raw e2, kept across the barrier).
#pragma unroll
            for (int k = 0; k < 8; k++) {
                float lo, hi; unpack2(t2[k], lo, hi);
                E[bb][k] = pack2(ex2f(lo), ex2f(hi));
            }
            // Inner-softmax denominator.
            u64 s01 = add2(add2(E[bb][0], E[bb][1]), add2(E[bb][2], E[bb][3]));
            u64 s23 = add2(add2(E[bb][4], E[bb][5]), add2(E[bb][6], E[bb][7]));
            u64 st  = add2(s01, s23);
            float slo, shi; unpack2(st, slo, shi);
            const float inv = rcpf(slo + shi);
            // Agreement dot with Vq.
            u64 g = mul2(E[bb][0], Vq2[0]);
#pragma unroll
            for (int k = 1; k < 8; k++) g = fma2(E[bb][k], Vq2[k], g);
            float glo, ghi; unpack2(g, glo, ghi);
            const float ag = (glo + ghi) * inv;
            stcs(agree_out + (((size_t)(b0 + bb) * NIN) + n0 + i) * MM + tid, ag);
            const float e = ex2f(ag * LOG2E);   // |ag| <= 1, max-free softmax safe
            eag[bb] = e;
            eag_p[bb] = e;
            inv_p[bb] = inv;
        }

        // ---- Warp partials of exp(ag); one barrier. ----
        float v0 = eag[0], v1 = eag[1];
#pragma unroll
        for (int o = 16; o > 0; o >>= 1) {
            v0 += __shfl_xor_sync(0xffffffffu, v0, o);
            v1 += __shfl_xor_sync(0xffffffffu, v1, o);
        }
        if (lane == 0) { sred[i & 1][wid] = v0; sred[i & 1][16 + wid] = v1; }
        __syncthreads();
    }

    // Final consume for iteration CHUNK-1 (its barrier already passed).
    {
        float z = sred[(CHUNK - 1) & 1][lane];
#pragma unroll
        for (int o = 8; o > 0; o >>= 1) z += __shfl_xor_sync(0xffffffffu, z, o);
        const float s0 = eag_p[0] * inv_p[0] * rcpf(__shfl_sync(0xffffffffu, z, 0));
        const float s1 = eag_p[1] * inv_p[1] * rcpf(__shfl_sync(0xffffffffu, z, 16));
        const u64 s0d = pack2(s0, s0);
        const u64 s1d = pack2(s1, s1);
#pragma unroll
        for (int k = 0; k < 8; k++) {
            acc2[0][k] = fma2(s0d, E[0][k], acc2[0][k]);
            acc2[1][k] = fma2(s1d, E[1][k], acc2[1][k]);
        }
    }

    // acc2[bb] as u64[8] is already float[16] in natural slot order.
#pragma unroll
    for (int bb = 0; bb < BPG; bb++) {
        float4* dst = (float4*)(g_partial +
            ((((size_t)chunk * BB + (b0 + bb)) * MM + tid) << 4));
#pragma unroll
        for (int q = 0; q < 4; q++) {
            float xx, yy, zz, ww;
            unpack2(acc2[bb][2 * q],     xx, yy);
            unpack2(acc2[bb][2 * q + 1], zz, ww);
            dst[q] = make_float4(xx, yy, zz, ww);
        }
    }
}

// Reduce chunk partials + LayerNorm. 8 lanes cooperate per (b,m) row:
// q = float4 quarter (0..3), h = chunk half (0..1).
__global__ __launch_bounds__(256)
void caps_ln(const float* __restrict__ gamma,
             const float* __restrict__ beta,
             float* __restrict__ nv_out)  // [B*MM, 16]
{
    const int t   = blockIdx.x * 256 + threadIdx.x;  // 0 .. B*MM*8-1
    const int row = t >> 3;
    const int q   = t & 3;
    const int h   = (t >> 2) & 1;
    const int b   = row / MM;
    const int m   = row % MM;

    float4 v = make_float4(0.f, 0.f, 0.f, 0.f);
#pragma unroll
    for (int cc = 0; cc < NCHUNK / 2; cc++) {
        const int c = h * (NCHUNK / 2) + cc;
        const float4 p = *(const float4*)(g_partial +
            ((((size_t)c * BB + b) * MM + m) << 4) + q * 4);
        v.x += p.x; v.y += p.y; v.z += p.z; v.w += p.w;
    }
    // Combine chunk halves (lanes differ in bit 2).
    v.x += __shfl_xor_sync(0xffffffffu, v.x, 4);
    v.y += __shfl_xor_sync(0xffffffffu, v.y, 4);
    v.z += __shfl_xor_sync(0xffffffffu, v.z, 4);
    v.w += __shfl_xor_sync(0xffffffffu, v.w, 4);

    // Row stats across the 4 q-lanes (bits 0-1).
    float s = v.x + v.y + v.z + v.w;
    s += __shfl_xor_sync(0xffffffffu, s, 1);
    s += __shfl_xor_sync(0xffffffffu, s, 2);
    const float mu = s * (1.0f / 16.0f);

    const float d0 = v.x - mu, d1 = v.y - mu, d2 = v.z - mu, d3 = v.w - mu;
    float ss = d0 * d0 + d1 * d1 + d2 * d2 + d3 * d3;
    ss += __shfl_xor_sync(0xffffffffu, ss, 1);
    ss += __shfl_xor_sync(0xffffffffu, ss, 2);
    const float rs = rsqrtf(ss * (1.0f / 16.0f) + LN_EPS);

    if (h == 0) {
        const float4 gm = *(const float4*)(gamma + q * 4);
        const float4 bt = *(const float4*)(beta + q * 4);
        float4 o;
        o.x = d0 * rs * gm.x + bt.x;
        o.y = d1 * rs * gm.y + bt.y;
        o.z = d2 * rs * gm.z + bt.z;
        o.w = d3 * rs * gm.w + bt.w;
        *(float4*)(nv_out + (size_t)row * 16 + q * 4) = o;
    }
}

extern "C" void kernel_launch(void* const* d_in, const int* in_sizes, int n_in,
                              void* d_out, int out_size)
{
    // metadata order: input, num_iter, w, V, gamma, beta
    const float* x     = (const float*)d_in[0];
    const float* w     = (const float*)d_in[2];
    const float* V     = (const float*)d_in[3];
    const float* gamma = (const float*)d_in[4];
    const float* beta  = (const float*)d_in[5];

    float* out    = (float*)d_out;
    float* nv_out = out;                          // [16,512,16]   = 131072
    float* agree  = out + (size_t)BB * MM * 16;   // [16,1024,512] = 8388608

    caps_main<<<NCHUNK * (BB / BPG), 512>>>(x, w, V, agree);
    caps_ln<<<(BB * MM * 8) / 256, 256>>>(gamma, beta, nv_out);
}